// round 9
// baseline (speedup 1.0000x reference)
#include <cuda_runtime.h>
#include <math.h>

// ---------------------------------------------------------------------------
// CausalEdgeAttention — algebraically reduced:
//   out = edge_attr + relu(nc@W1eff + b1) @ Meff + c2
//   nc    = nf[src]+nf[tgt]          (0.5 folded into W1eff = 0.5*n_W1)
//   Meff  = 0.5 * diag(scale) * M,   M = n_W2 @ Wv @ Wo @ Wp
//   c2    = 0.5 * (b2@R2 + bv@R1 + bo@Wp + bp + shift@M)
//   scale = gamma*rsqrt(var+eps), shift = beta - mu*scale (BN stats of h1)
// Edge encoder in the reference is dead code -> skipped.
// stats: tf32 tensor-core, 256-edge rounds. folds: one 1024-thread block,
// 3 phases with k-split 4. reduce: block-per-channel. main: R4 proven scalar.
// ---------------------------------------------------------------------------

#define HDIM 256
#define DDIM 8
#define SGRID 512

typedef unsigned long long u64;
typedef unsigned int u32;

__device__ __forceinline__ u64 pk(float lo, float hi) {
    u64 r; asm("mov.b64 %0,{%1,%2};" : "=l"(r) : "f"(lo), "f"(hi)); return r;
}
__device__ __forceinline__ void upk(u64 v, float& lo, float& hi) {
    asm("mov.b64 {%0,%1},%2;" : "=f"(lo), "=f"(hi) : "l"(v));
}
__device__ __forceinline__ u64 f2mul(u64 a, u64 b) {
    u64 d; asm("mul.rn.f32x2 %0,%1,%2;" : "=l"(d) : "l"(a), "l"(b)); return d;
}
__device__ __forceinline__ u64 f2add(u64 a, u64 b) {
    u64 d; asm("add.rn.f32x2 %0,%1,%2;" : "=l"(d) : "l"(a), "l"(b)); return d;
}
__device__ __forceinline__ u64 f2fma(u64 a, u64 b, u64 c) {
    u64 d; asm("fma.rn.f32x2 %0,%1,%2,%3;" : "=l"(d) : "l"(a), "l"(b), "l"(c)); return d;
}
__device__ __forceinline__ u32 cvt_tf32(float f) {
    u32 r; asm("cvt.rna.tf32.f32 %0, %1;" : "=r"(r) : "f"(f)); return r;
}

// ------------------------- scratch (device globals; no allocs) -------------
__device__ float  g_R1[HDIM * DDIM];   // Wo @ Wp
__device__ float  g_R2[HDIM * DDIM];   // Wv @ R1
__device__ float  g_M [HDIM * DDIM];   // n_W2 @ R2
__device__ float2 g_ps[SGRID * HDIM];  // BN partials (sum, sumsq)
__device__ float  g_scl[HDIM];         // BN scale per channel
__device__ float  g_shf[HDIM];         // BN shift per channel
__device__ u64    g_Meff[HDIM * 4];    // packed d-pairs: 0.5*scale[h]*M[h][:]
__device__ float  g_c2[DDIM];

// ------------------------- pass A: BN statistics via tf32 MMA --------------
// 256-edge rounds: all threads stage one edge; 16 MMA subtiles per round.
__global__ void __launch_bounds__(256) stats_kernel(const float* __restrict__ nf,
                                                    const int* __restrict__ ei0,
                                                    const int* __restrict__ ei1,
                                                    const float* __restrict__ W1,
                                                    const float* __restrict__ b1,
                                                    int fullE) {
    __shared__ float aS[4][16][32];   // [A-frag slot][subtile][lane]
    int t = threadIdx.x, w = t >> 5, l = t & 31;
    int g = l >> 2, c = l & 3;

    u32 Bf0[4], Bf1[4];
    float cbl[4], cbh[4];
#pragma unroll
    for (int jj = 0; jj < 4; jj++) {
        int j = 4 * w + jj, n = 8 * j + g;
        Bf0[jj] = cvt_tf32(0.5f * __ldg(W1 + c * HDIM + n));
        Bf1[jj] = cvt_tf32(0.5f * __ldg(W1 + (c + 4) * HDIM + n));
        cbl[jj] = __ldg(b1 + 8 * j + 2 * c);
        cbh[jj] = __ldg(b1 + 8 * j + 2 * c + 1);
    }
    float sL[4] = {0.f, 0.f, 0.f, 0.f}, sH[4] = {0.f, 0.f, 0.f, 0.f};
    float qL[4] = {0.f, 0.f, 0.f, 0.f}, qH[4] = {0.f, 0.f, 0.f, 0.f};
    const float4* nfp = (const float4*)nf;

    for (int base = blockIdx.x * 256; base < fullE; base += SGRID * 256) {
        __syncthreads();
        {
            int e = base + t;
            if (e < fullE) {
                int r = t & 15, tt = t >> 4;
                int si = __ldg(ei0 + e), ti = __ldg(ei1 + e);
                float4 s0 = __ldg(nfp + 2 * si), s1 = __ldg(nfp + 2 * si + 1);
                float4 u0 = __ldg(nfp + 2 * ti), u1 = __ldg(nfp + 2 * ti + 1);
                float v[8];
                v[0] = s0.x + u0.x; v[1] = s0.y + u0.y;
                v[2] = s0.z + u0.z; v[3] = s0.w + u0.w;
                v[4] = s1.x + u1.x; v[5] = s1.y + u1.y;
                v[6] = s1.z + u1.z; v[7] = s1.w + u1.w;
                int rr = r & 7, hi = r >> 3;
#pragma unroll
                for (int cc = 0; cc < 4; cc++) {
                    aS[hi][tt][rr * 4 + cc]     = __uint_as_float(cvt_tf32(v[cc]));
                    aS[2 + hi][tt][rr * 4 + cc] = __uint_as_float(cvt_tf32(v[cc + 4]));
                }
            }
        }
        __syncthreads();
#pragma unroll
        for (int tt = 0; tt < 16; tt++) {
            if (base + 16 * tt >= fullE) break;
            u32 A0 = __float_as_uint(aS[0][tt][l]);
            u32 A1 = __float_as_uint(aS[1][tt][l]);
            u32 A2 = __float_as_uint(aS[2][tt][l]);
            u32 A3 = __float_as_uint(aS[3][tt][l]);
#pragma unroll
            for (int jj = 0; jj < 4; jj++) {
                float d0, d1, d2, d3;
                asm volatile(
                    "mma.sync.aligned.m16n8k8.row.col.f32.tf32.tf32.f32 "
                    "{%0,%1,%2,%3}, {%4,%5,%6,%7}, {%8,%9}, {%10,%11,%12,%13};\n"
                    : "=f"(d0), "=f"(d1), "=f"(d2), "=f"(d3)
                    : "r"(A0), "r"(A1), "r"(A2), "r"(A3),
                      "r"(Bf0[jj]), "r"(Bf1[jj]),
                      "f"(cbl[jj]), "f"(cbh[jj]), "f"(cbl[jj]), "f"(cbh[jj]));
                float r0 = fmaxf(d0, 0.f), r1 = fmaxf(d1, 0.f);
                float r2 = fmaxf(d2, 0.f), r3 = fmaxf(d3, 0.f);
                sL[jj] += r0 + r2;
                sH[jj] += r1 + r3;
                qL[jj] = fmaf(r0, r0, qL[jj]); qL[jj] = fmaf(r2, r2, qL[jj]);
                qH[jj] = fmaf(r1, r1, qH[jj]); qH[jj] = fmaf(r3, r3, qH[jj]);
            }
        }
    }
#pragma unroll
    for (int jj = 0; jj < 4; jj++)
#pragma unroll
        for (int off = 4; off <= 16; off <<= 1) {
            sL[jj] += __shfl_xor_sync(0xffffffffu, sL[jj], off);
            sH[jj] += __shfl_xor_sync(0xffffffffu, sH[jj], off);
            qL[jj] += __shfl_xor_sync(0xffffffffu, qL[jj], off);
            qH[jj] += __shfl_xor_sync(0xffffffffu, qH[jj], off);
        }
    if (g == 0) {
#pragma unroll
        for (int jj = 0; jj < 4; jj++) {
            int ch = 8 * (4 * w + jj) + 2 * c;
            g_ps[blockIdx.x * HDIM + ch]     = make_float2(sL[jj], qL[jj]);
            g_ps[blockIdx.x * HDIM + ch + 1] = make_float2(sH[jj], qH[jj]);
        }
    }
}

// ------------------------- merged folds: one block, 3 phases ---------------
// 1024 threads: thread = (row h = t>>2, part p = t&3, k-range 64p..64p+63).
// Double-buffered B pairs in smem; partials reduced by p==0 threads.
__global__ void __launch_bounds__(1024) fold_merged_kernel(const float* __restrict__ Wo,
                                                           const float* __restrict__ Wv,
                                                           const float* __restrict__ nW2,
                                                           const float* __restrict__ Wp) {
    __shared__ u64 Bs[2][HDIM * 4];
    __shared__ u64 pt[1024 * 4];
    int t = threadIdx.x;
    int h = t >> 2, p = t & 3;

    // load Wp pairs into buffer 0
    const u64* wpp = (const u64*)Wp;
    for (int i = t; i < HDIM * 4; i += 1024) Bs[0][i] = wpp[i];
    __syncthreads();

    const float* As[3] = {Wo, Wv, nW2};
    float* Gs[3] = {g_R1, g_R2, g_M};
#pragma unroll 1
    for (int ph = 0; ph < 3; ph++) {
        const u64* Bc = Bs[ph & 1];
        const float* Ar = As[ph] + h * HDIM + 64 * p;
        u64 a0 = 0, a1 = 0, a2 = 0, a3 = 0;
#pragma unroll 8
        for (int k = 0; k < 64; k++) {
            float a = __ldg(Ar + k);
            u64 aa = pk(a, a);
            const u64* bk = Bc + (64 * p + k) * 4;
            a0 = f2fma(aa, bk[0], a0);
            a1 = f2fma(aa, bk[1], a1);
            a2 = f2fma(aa, bk[2], a2);
            a3 = f2fma(aa, bk[3], a3);
        }
        pt[t * 4 + 0] = a0; pt[t * 4 + 1] = a1;
        pt[t * 4 + 2] = a2; pt[t * 4 + 3] = a3;
        __syncthreads();
        if (p == 0) {
            u64* Bn = Bs[(ph + 1) & 1];
            u64* go = (u64*)Gs[ph];
#pragma unroll
            for (int j = 0; j < 4; j++) {
                u64 s = f2add(f2add(pt[(4 * h) * 4 + j], pt[(4 * h + 1) * 4 + j]),
                              f2add(pt[(4 * h + 2) * 4 + j], pt[(4 * h + 3) * 4 + j]));
                Bn[h * 4 + j] = s;
                go[h * 4 + j] = s;
            }
        }
        __syncthreads();
    }
}

// ------------------------- BN reduce: one block per channel ----------------
__global__ void __launch_bounds__(256) reduce_kernel(const float* __restrict__ gamma,
                                                     const float* __restrict__ beta,
                                                     const float* __restrict__ nf,
                                                     const int* __restrict__ ei0,
                                                     const int* __restrict__ ei1,
                                                     const float* __restrict__ W1,
                                                     const float* __restrict__ b1,
                                                     int fullE, int E) {
    __shared__ float ss[8], qq[8];
    int h = blockIdx.x, t = threadIdx.x;
    float2 p0 = g_ps[t * HDIM + h];
    float2 p1 = g_ps[(t + 256) * HDIM + h];
    float s = p0.x + p1.x, q = p0.y + p1.y;
#pragma unroll
    for (int off = 16; off; off >>= 1) {
        s += __shfl_xor_sync(0xffffffffu, s, off);
        q += __shfl_xor_sync(0xffffffffu, q, off);
    }
    if ((t & 31) == 0) { ss[t >> 5] = s; qq[t >> 5] = q; }
    __syncthreads();
    if (t == 0) {
        s = 0.f; q = 0.f;
#pragma unroll
        for (int i = 0; i < 8; i++) { s += ss[i]; q += qq[i]; }
        for (int e = fullE; e < E; e++) {
            int si = __ldg(ei0 + e), ti = __ldg(ei1 + e);
            float z = __ldg(b1 + h);
#pragma unroll
            for (int k = 0; k < 8; k++)
                z = fmaf(0.5f * (__ldg(nf + si * 8 + k) + __ldg(nf + ti * 8 + k)),
                         __ldg(W1 + k * HDIM + h), z);
            float hv = fmaxf(z, 0.f);
            s += hv; q = fmaf(hv, hv, q);
        }
        float invE = 1.0f / (float)E;
        float mu = s * invE;
        float var = fmaxf(q * invE - mu * mu, 0.f);
        float scl = gamma[h] * rsqrtf(var + 1e-5f);
        g_scl[h] = scl;
        g_shf[h] = beta[h] - mu * scl;
    }
}

// ------------------------- final: pack Meff + compute c2 -------------------
__global__ void __launch_bounds__(256) final_kernel(const float* __restrict__ b2,
                                                    const float* __restrict__ bv,
                                                    const float* __restrict__ bo,
                                                    const float* __restrict__ bp,
                                                    const float* __restrict__ Wp) {
    int t = threadIdx.x;
    float scl = g_scl[t];
#pragma unroll
    for (int p = 0; p < 4; p++)
        g_Meff[t * 4 + p] = pk(0.5f * scl * g_M[t * 8 + 2 * p],
                               0.5f * scl * g_M[t * 8 + 2 * p + 1]);

    int w = t >> 5, lane = t & 31;
    if (w < DDIM) {
        float r = 0.f;
#pragma unroll
        for (int i = 0; i < 8; i++) {
            int h = lane + 32 * i;
            r += g_shf[h] * g_M[h * 8 + w] + __ldg(b2 + h) * g_R2[h * 8 + w]
               + __ldg(bv + h) * g_R1[h * 8 + w] + __ldg(bo + h) * __ldg(Wp + h * 8 + w);
        }
#pragma unroll
        for (int off = 16; off; off >>= 1) r += __shfl_xor_sync(0xffffffffu, r, off);
        if (lane == 0) g_c2[w] = 0.5f * (__ldg(bp + w) + r);
    }
}

// ------------------------- pass B: main (exact R4 proven config) -----------
__global__ void __launch_bounds__(256, 2) main_kernel(const float* __restrict__ edge_attr,
                                                      const float* __restrict__ nf,
                                                      const int* __restrict__ ei0,
                                                      const int* __restrict__ ei1,
                                                      const float* __restrict__ W1,
                                                      const float* __restrict__ b1,
                                                      float* __restrict__ out,
                                                      int E) {
    __shared__ u64 wp[HDIM * 4];
    __shared__ u64 mp[HDIM * 4];
    __shared__ float b1s[HDIM];
    int t = threadIdx.x;
    for (int idx = t; idx < HDIM * 4; idx += 256) {
        int h = idx >> 2, p = idx & 3;
        wp[idx] = pk(0.5f * W1[(2 * p) * HDIM + h], 0.5f * W1[(2 * p + 1) * HDIM + h]);
        mp[idx] = g_Meff[idx];
    }
    b1s[t] = b1[t];
    __syncthreads();

    int base = (blockIdx.x * 256 + t) * 4;
    if (base >= E) return;

    int ee[4];
#pragma unroll
    for (int i = 0; i < 4; i++) ee[i] = min(base + i, E - 1);

    const float4* nfp = (const float4*)nf;
    u64 n[4][4];
#pragma unroll
    for (int i = 0; i < 4; i++) {
        int s = __ldg(ei0 + ee[i]), g = __ldg(ei1 + ee[i]);
        float4 a0 = __ldg(nfp + 2 * s), a1 = __ldg(nfp + 2 * s + 1);
        float4 c0 = __ldg(nfp + 2 * g), c1 = __ldg(nfp + 2 * g + 1);
        n[i][0] = pk(a0.x + c0.x, a0.y + c0.y);
        n[i][1] = pk(a0.z + c0.z, a0.w + c0.w);
        n[i][2] = pk(a1.x + c1.x, a1.y + c1.y);
        n[i][3] = pk(a1.z + c1.z, a1.w + c1.w);
    }

    u64 acc[4][4];
#pragma unroll
    for (int i = 0; i < 4; i++)
#pragma unroll
        for (int p = 0; p < 4; p++) acc[i][p] = 0;

#pragma unroll 2
    for (int h = 0; h < HDIM; h++) {
        u64 w0 = wp[h * 4 + 0], w1 = wp[h * 4 + 1], w2 = wp[h * 4 + 2], w3 = wp[h * 4 + 3];
        u64 m0 = mp[h * 4 + 0], m1 = mp[h * 4 + 1], m2 = mp[h * 4 + 2], m3 = mp[h * 4 + 3];
        float bb = b1s[h];
#pragma unroll
        for (int i = 0; i < 4; i++) {
            u64 s_ = f2mul(n[i][0], w0);
            s_ = f2fma(n[i][1], w1, s_);
            s_ = f2fma(n[i][2], w2, s_);
            s_ = f2fma(n[i][3], w3, s_);
            float lo, hi; upk(s_, lo, hi);
            float h1 = fmaxf(lo + hi + bb, 0.f);
            u64 hh = pk(h1, h1);
            acc[i][0] = f2fma(hh, m0, acc[i][0]);
            acc[i][1] = f2fma(hh, m1, acc[i][1]);
            acc[i][2] = f2fma(hh, m2, acc[i][2]);
            acc[i][3] = f2fma(hh, m3, acc[i][3]);
        }
    }

    float cz[8];
#pragma unroll
    for (int d = 0; d < 8; d++) cz[d] = g_c2[d];

    const float4* eap = (const float4*)edge_attr;
    float4* outp = (float4*)out;
#pragma unroll
    for (int i = 0; i < 4; i++) {
        int e = base + i;
        if (e >= E) break;
        float4 e0 = __ldg(eap + e * 2), e1 = __ldg(eap + e * 2 + 1);
        float x0, x1, x2, x3, x4, x5, x6, x7;
        upk(acc[i][0], x0, x1); upk(acc[i][1], x2, x3);
        upk(acc[i][2], x4, x5); upk(acc[i][3], x6, x7);
        float4 o0, o1;
        o0.x = e0.x + x0 + cz[0]; o0.y = e0.y + x1 + cz[1];
        o0.z = e0.z + x2 + cz[2]; o0.w = e0.w + x3 + cz[3];
        o1.x = e1.x + x4 + cz[4]; o1.y = e1.y + x5 + cz[5];
        o1.z = e1.z + x6 + cz[6]; o1.w = e1.w + x7 + cz[7];
        outp[e * 2] = o0; outp[e * 2 + 1] = o1;
    }
}

// ------------------------- launch ------------------------------------------
extern "C" void kernel_launch(void* const* d_in, const int* in_sizes, int n_in,
                              void* d_out, int out_size) {
    const float* edge_attr = (const float*)d_in[0];
    const float* nf        = (const float*)d_in[1];
    const int*   ei        = (const int*)  d_in[2];
    // d_in[3..8] = edge encoder params: dead code in the reference, unused.
    const float* nW1   = (const float*)d_in[9];
    const float* nb1   = (const float*)d_in[10];
    const float* ngam  = (const float*)d_in[11];
    const float* nbet  = (const float*)d_in[12];
    const float* nW2   = (const float*)d_in[13];
    const float* nb2   = (const float*)d_in[14];
    const float* Wv    = (const float*)d_in[15];
    const float* bv    = (const float*)d_in[16];
    const float* Wo    = (const float*)d_in[17];
    const float* bo    = (const float*)d_in[18];
    const float* Wp    = (const float*)d_in[19];
    const float* bp    = (const float*)d_in[20];
    (void)n_in; (void)out_size;

    int E = in_sizes[0] / DDIM;
    const int* ei0 = ei;
    const int* ei1 = ei + E;
    float* out = (float*)d_out;
    int fullE = (E / 16) * 16;

    // BN statistics via tensor cores (longest chain starts immediately)
    stats_kernel<<<SGRID, 256>>>(nf, ei0, ei1, nW1, nb1, fullE);

    // all three weight folds, one kernel
    fold_merged_kernel<<<1, 1024>>>(Wo, Wv, nW2, Wp);

    // BN finalize: parallel partials reduce, then tiny pack kernel
    reduce_kernel<<<HDIM, 256>>>(ngam, nbet, nf, ei0, ei1, nW1, nb1, fullE, E);
    final_kernel<<<1, 256>>>(nb2, bv, bo, bp, Wp);

    // main fused pass, 4 edges / thread (exact R4 config)
    int gridB = (E + 1023) / 1024;
    main_kernel<<<gridB, 256>>>(edge_attr, nf, ei0, ei1, nW1, nb1, out, E);
}

// round 10
// speedup vs baseline: 1.7493x; 1.7493x over previous
#include <cuda_runtime.h>
#include <math.h>

// ---------------------------------------------------------------------------
// CausalEdgeAttention — algebraically reduced:
//   out = edge_attr + relu(nc@W1eff + b1) @ Meff + c2
//   nc    = nf[src]+nf[tgt]          (0.5 folded into W1eff = 0.5*n_W1)
//   Meff  = 0.5 * diag(scale) * M,   M = n_W2 @ Wv @ Wo @ Wp
//   c2    = 0.5 * (b2@R2 + bv@R1 + bo@Wp + bp + shift@M)
//   scale = gamma*rsqrt(var+eps), shift = beta - mu*scale (BN stats of h1)
// Edge encoder in the reference is dead code -> skipped.
// stats: tf32 MMA, 128-edge rounds (R8 proven). folds/reduce/final: R8 proven.
// main: tf32 MMA for z; lane-local scalar f32x2 accumulation for h1@Meff
//       (no per-chunk shuffle repack); one 2-round butterfly per 16-edge tile.
// ---------------------------------------------------------------------------

#define HDIM 256
#define DDIM 8
#define SGRID 512
#define TPW 4

typedef unsigned long long u64;
typedef unsigned int u32;

__device__ __forceinline__ u64 pk(float lo, float hi) {
    u64 r; asm("mov.b64 %0,{%1,%2};" : "=l"(r) : "f"(lo), "f"(hi)); return r;
}
__device__ __forceinline__ void upk(u64 v, float& lo, float& hi) {
    asm("mov.b64 {%0,%1},%2;" : "=f"(lo), "=f"(hi) : "l"(v));
}
__device__ __forceinline__ u64 f2add(u64 a, u64 b) {
    u64 d; asm("add.rn.f32x2 %0,%1,%2;" : "=l"(d) : "l"(a), "l"(b)); return d;
}
__device__ __forceinline__ u64 f2fma(u64 a, u64 b, u64 c) {
    u64 d; asm("fma.rn.f32x2 %0,%1,%2,%3;" : "=l"(d) : "l"(a), "l"(b), "l"(c)); return d;
}
__device__ __forceinline__ u32 cvt_tf32(float f) {
    u32 r; asm("cvt.rna.tf32.f32 %0, %1;" : "=r"(r) : "f"(f)); return r;
}

// ------------------------- scratch (device globals; no allocs) -------------
__device__ float  g_R1[HDIM * DDIM];   // Wo @ Wp
__device__ float  g_R2[HDIM * DDIM];   // Wv @ R1
__device__ float  g_M [HDIM * DDIM];   // n_W2 @ R2
__device__ float2 g_ps[SGRID * HDIM];  // BN partials (sum, sumsq)
__device__ float  g_scl[HDIM];         // BN scale per channel
__device__ float  g_shf[HDIM];         // BN shift per channel
__device__ u64    g_Meff[HDIM * 4];    // packed d-pairs: 0.5*scale[h]*M[h][:]
__device__ float2 g_zB[1024];          // z-GEMM B-frags (tf32 bits), R5 layout
__device__ float  g_c2[DDIM];

// ------------------------- pass A: BN statistics via tf32 MMA (R8) ---------
__global__ void __launch_bounds__(256) stats_kernel(const float* __restrict__ nf,
                                                    const int* __restrict__ ei0,
                                                    const int* __restrict__ ei1,
                                                    const float* __restrict__ W1,
                                                    const float* __restrict__ b1,
                                                    int fullE) {
    __shared__ float aS[4][8][32];
    int t = threadIdx.x, w = t >> 5, l = t & 31;
    int g = l >> 2, c = l & 3;

    u32 Bf0[4], Bf1[4];
    float cbl[4], cbh[4];
#pragma unroll
    for (int jj = 0; jj < 4; jj++) {
        int j = 4 * w + jj, n = 8 * j + g;
        Bf0[jj] = cvt_tf32(0.5f * __ldg(W1 + c * HDIM + n));
        Bf1[jj] = cvt_tf32(0.5f * __ldg(W1 + (c + 4) * HDIM + n));
        cbl[jj] = __ldg(b1 + 8 * j + 2 * c);
        cbh[jj] = __ldg(b1 + 8 * j + 2 * c + 1);
    }
    float sL[4] = {0.f, 0.f, 0.f, 0.f}, sH[4] = {0.f, 0.f, 0.f, 0.f};
    float qL[4] = {0.f, 0.f, 0.f, 0.f}, qH[4] = {0.f, 0.f, 0.f, 0.f};
    const float4* nfp = (const float4*)nf;

    for (int base = blockIdx.x * 128; base < fullE; base += SGRID * 128) {
        __syncthreads();
        if (t < 128) {
            int e = base + t;
            if (e < fullE) {
                int r = t & 15, tt = t >> 4;
                int si = __ldg(ei0 + e), ti = __ldg(ei1 + e);
                float4 s0 = __ldg(nfp + 2 * si), s1 = __ldg(nfp + 2 * si + 1);
                float4 u0 = __ldg(nfp + 2 * ti), u1 = __ldg(nfp + 2 * ti + 1);
                float v[8];
                v[0] = s0.x + u0.x; v[1] = s0.y + u0.y;
                v[2] = s0.z + u0.z; v[3] = s0.w + u0.w;
                v[4] = s1.x + u1.x; v[5] = s1.y + u1.y;
                v[6] = s1.z + u1.z; v[7] = s1.w + u1.w;
                int rr = r & 7, hi = r >> 3;
#pragma unroll
                for (int cc = 0; cc < 4; cc++) {
                    aS[hi][tt][rr * 4 + cc]     = __uint_as_float(cvt_tf32(v[cc]));
                    aS[2 + hi][tt][rr * 4 + cc] = __uint_as_float(cvt_tf32(v[cc + 4]));
                }
            }
        }
        __syncthreads();
#pragma unroll
        for (int tt = 0; tt < 8; tt++) {
            if (base + 16 * tt >= fullE) break;
            u32 A0 = __float_as_uint(aS[0][tt][l]);
            u32 A1 = __float_as_uint(aS[1][tt][l]);
            u32 A2 = __float_as_uint(aS[2][tt][l]);
            u32 A3 = __float_as_uint(aS[3][tt][l]);
#pragma unroll
            for (int jj = 0; jj < 4; jj++) {
                float d0, d1, d2, d3;
                asm volatile(
                    "mma.sync.aligned.m16n8k8.row.col.f32.tf32.tf32.f32 "
                    "{%0,%1,%2,%3}, {%4,%5,%6,%7}, {%8,%9}, {%10,%11,%12,%13};\n"
                    : "=f"(d0), "=f"(d1), "=f"(d2), "=f"(d3)
                    : "r"(A0), "r"(A1), "r"(A2), "r"(A3),
                      "r"(Bf0[jj]), "r"(Bf1[jj]),
                      "f"(cbl[jj]), "f"(cbh[jj]), "f"(cbl[jj]), "f"(cbh[jj]));
                float r0 = fmaxf(d0, 0.f), r1 = fmaxf(d1, 0.f);
                float r2 = fmaxf(d2, 0.f), r3 = fmaxf(d3, 0.f);
                sL[jj] += r0 + r2;
                sH[jj] += r1 + r3;
                qL[jj] = fmaf(r0, r0, qL[jj]); qL[jj] = fmaf(r2, r2, qL[jj]);
                qH[jj] = fmaf(r1, r1, qH[jj]); qH[jj] = fmaf(r3, r3, qH[jj]);
            }
        }
    }
#pragma unroll
    for (int jj = 0; jj < 4; jj++)
#pragma unroll
        for (int off = 4; off <= 16; off <<= 1) {
            sL[jj] += __shfl_xor_sync(0xffffffffu, sL[jj], off);
            sH[jj] += __shfl_xor_sync(0xffffffffu, sH[jj], off);
            qL[jj] += __shfl_xor_sync(0xffffffffu, qL[jj], off);
            qH[jj] += __shfl_xor_sync(0xffffffffu, qH[jj], off);
        }
    if (g == 0) {
#pragma unroll
        for (int jj = 0; jj < 4; jj++) {
            int ch = 8 * (4 * w + jj) + 2 * c;
            g_ps[blockIdx.x * HDIM + ch]     = make_float2(sL[jj], qL[jj]);
            g_ps[blockIdx.x * HDIM + ch + 1] = make_float2(sH[jj], qH[jj]);
        }
    }
}

// ------------------------- fold: Out[H,8] = A[H,H] @ B[H,8] (R8 proven) ----
__global__ void __launch_bounds__(256) fold_kernel(const float* __restrict__ A,
                                                   const float* __restrict__ Bext,
                                                   int mode) {
    __shared__ u64 Bs[HDIM * 4];
    const u64* Bv = (mode == 0) ? (const u64*)Bext
                   : (mode == 1) ? (const u64*)g_R1 : (const u64*)g_R2;
    float* Out = (mode == 0) ? g_R1 : (mode == 1) ? g_R2 : g_M;
    int t = threadIdx.x;
    for (int i = t; i < HDIM * 4; i += 256) Bs[i] = Bv[i];
    __syncthreads();

    int h = blockIdx.x * 8 + (t >> 5);
    int lane = t & 31;
    const float* Ar = A + h * HDIM;
    u64 a0 = 0, a1 = 0, a2 = 0, a3 = 0;
#pragma unroll
    for (int i = 0; i < 8; i++) {
        int k = lane + 32 * i;
        float a = __ldg(Ar + k);
        u64 aa = pk(a, a);
        a0 = f2fma(aa, Bs[k * 4 + 0], a0);
        a1 = f2fma(aa, Bs[k * 4 + 1], a1);
        a2 = f2fma(aa, Bs[k * 4 + 2], a2);
        a3 = f2fma(aa, Bs[k * 4 + 3], a3);
    }
    float r[8];
    upk(a0, r[0], r[1]); upk(a1, r[2], r[3]);
    upk(a2, r[4], r[5]); upk(a3, r[6], r[7]);
#pragma unroll
    for (int off = 16; off; off >>= 1)
#pragma unroll
        for (int d = 0; d < 8; d++) r[d] += __shfl_xor_sync(0xffffffffu, r[d], off);
    if (lane == 0) {
        float4* o = (float4*)(Out + h * 8);
        o[0] = make_float4(r[0], r[1], r[2], r[3]);
        o[1] = make_float4(r[4], r[5], r[6], r[7]);
    }
}

// ------------------------- BN reduce: one block per channel (R8) -----------
__global__ void __launch_bounds__(256) reduce_kernel(const float* __restrict__ gamma,
                                                     const float* __restrict__ beta,
                                                     const float* __restrict__ nf,
                                                     const int* __restrict__ ei0,
                                                     const int* __restrict__ ei1,
                                                     const float* __restrict__ W1,
                                                     const float* __restrict__ b1,
                                                     int fullE, int E) {
    __shared__ float ss[8], qq[8];
    int h = blockIdx.x, t = threadIdx.x;
    float2 p0 = g_ps[t * HDIM + h];
    float2 p1 = g_ps[(t + 256) * HDIM + h];
    float s = p0.x + p1.x, q = p0.y + p1.y;
#pragma unroll
    for (int off = 16; off; off >>= 1) {
        s += __shfl_xor_sync(0xffffffffu, s, off);
        q += __shfl_xor_sync(0xffffffffu, q, off);
    }
    if ((t & 31) == 0) { ss[t >> 5] = s; qq[t >> 5] = q; }
    __syncthreads();
    if (t == 0) {
        s = 0.f; q = 0.f;
#pragma unroll
        for (int i = 0; i < 8; i++) { s += ss[i]; q += qq[i]; }
        for (int e = fullE; e < E; e++) {
            int si = __ldg(ei0 + e), ti = __ldg(ei1 + e);
            float z = __ldg(b1 + h);
#pragma unroll
            for (int k = 0; k < 8; k++)
                z = fmaf(0.5f * (__ldg(nf + si * 8 + k) + __ldg(nf + ti * 8 + k)),
                         __ldg(W1 + k * HDIM + h), z);
            float hv = fmaxf(z, 0.f);
            s += hv; q = fmaf(hv, hv, q);
        }
        float invE = 1.0f / (float)E;
        float mu = s * invE;
        float var = fmaxf(q * invE - mu * mu, 0.f);
        float scl = gamma[h] * rsqrtf(var + 1e-5f);
        g_scl[h] = scl;
        g_shf[h] = beta[h] - mu * scl;
    }
}

// ------------------------- final: pack Meff + zB-frags + c2 ----------------
__global__ void __launch_bounds__(256) final_kernel(const float* __restrict__ b2,
                                                    const float* __restrict__ bv,
                                                    const float* __restrict__ bo,
                                                    const float* __restrict__ bp,
                                                    const float* __restrict__ Wp,
                                                    const float* __restrict__ W1) {
    int t = threadIdx.x;
    float scl = g_scl[t];
#pragma unroll
    for (int p = 0; p < 4; p++)
        g_Meff[t * 4 + p] = pk(0.5f * scl * g_M[t * 8 + 2 * p],
                               0.5f * scl * g_M[t * 8 + 2 * p + 1]);

    // z-GEMM B-fragments, R5-proven layout: b0=B[k=l&3][n], b1=B[k=l&3+4][n]
    for (int idx = t; idx < 1024; idx += 256) {
        int j = idx >> 5, l = idx & 31;
        int n = 8 * j + (l >> 2);
        int k0 = l & 3;
        g_zB[idx] = make_float2(
            __uint_as_float(cvt_tf32(0.5f * __ldg(W1 + k0 * HDIM + n))),
            __uint_as_float(cvt_tf32(0.5f * __ldg(W1 + (k0 + 4) * HDIM + n))));
    }

    int w = t >> 5, lane = t & 31;
    if (w < DDIM) {
        float r = 0.f;
#pragma unroll
        for (int i = 0; i < 8; i++) {
            int h = lane + 32 * i;
            r += g_shf[h] * g_M[h * 8 + w] + __ldg(b2 + h) * g_R2[h * 8 + w]
               + __ldg(bv + h) * g_R1[h * 8 + w] + __ldg(bo + h) * __ldg(Wp + h * 8 + w);
        }
#pragma unroll
        for (int off = 16; off; off >>= 1) r += __shfl_xor_sync(0xffffffffu, r, off);
        if (lane == 0) g_c2[w] = 0.5f * (__ldg(bp + w) + r);
    }
}

// ------------------------- pass B: MMA-z main, lane-local out accum --------
__global__ void __launch_bounds__(256) main_kernel(const float* __restrict__ edge_attr,
                                                   const float* __restrict__ nf,
                                                   const int* __restrict__ ei0,
                                                   const int* __restrict__ ei1,
                                                   const float* __restrict__ b1,
                                                   float* __restrict__ out,
                                                   int E, int ntiles) {
    __shared__ float2 zBs[1024];
    __shared__ ulonglong2 mps[HDIM * 2];   // Meff row n at mps[n*2], [n*2+1]
    __shared__ float b1s[HDIM];
    __shared__ float ncs[8][16 * 10];      // per-warp staged nc tile, pad 10
    int t = threadIdx.x;
    {
        const float2* zg = (const float2*)g_zB;
        const ulonglong2* mg = (const ulonglong2*)g_Meff;
        for (int i = t; i < 1024; i += 256) zBs[i] = zg[i];
        for (int i = t; i < HDIM * 2; i += 256) mps[i] = mg[i];
        b1s[t] = b1[t];
    }
    __syncthreads();

    int w = t >> 5, lane = t & 31;
    int g = lane >> 2, c = lane & 3;
    float czl = g_c2[2 * c], czh = g_c2[2 * c + 1];
    float* nw = ncs[w];
    const float4* nfp = (const float4*)nf;

    int tile0 = (blockIdx.x * 8 + w) * TPW;
#pragma unroll 1
    for (int tt = 0; tt < TPW; tt++) {
        int tile = tile0 + tt;
        if (tile >= ntiles) break;
        int base = tile * 16;

        __syncwarp();
        if (lane < 16) {
            int e = min(base + lane, E - 1);
            int si = __ldg(ei0 + e), ti = __ldg(ei1 + e);
            float4 s0 = __ldg(nfp + 2 * si), s1 = __ldg(nfp + 2 * si + 1);
            float4 u0 = __ldg(nfp + 2 * ti), u1 = __ldg(nfp + 2 * ti + 1);
            float2* p = (float2*)(nw + lane * 10);
            p[0] = make_float2(s0.x + u0.x, s0.y + u0.y);
            p[1] = make_float2(s0.z + u0.z, s0.w + u0.w);
            p[2] = make_float2(s1.x + u1.x, s1.y + u1.y);
            p[3] = make_float2(s1.z + u1.z, s1.w + u1.w);
        }
        __syncwarp();

        u32 A0 = cvt_tf32(nw[g * 10 + c]);
        u32 A1 = cvt_tf32(nw[(g + 8) * 10 + c]);
        u32 A2 = cvt_tf32(nw[g * 10 + c + 4]);
        u32 A3 = cvt_tf32(nw[(g + 8) * 10 + c + 4]);

        u64 aL0 = 0, aL1 = 0, aL2 = 0, aL3 = 0;   // edge base+g,   d-pairs 0..3
        u64 aH0 = 0, aH1 = 0, aH2 = 0, aH3 = 0;   // edge base+g+8, d-pairs 0..3
#pragma unroll
        for (int j = 0; j < 32; j++) {
            float2 cb = *(const float2*)(b1s + 8 * j + 2 * c);
            float2 wz = zBs[j * 32 + lane];
            u32 wz0 = __float_as_uint(wz.x), wz1 = __float_as_uint(wz.y);
            float z0, z1, z2, z3;
            asm volatile(
                "mma.sync.aligned.m16n8k8.row.col.f32.tf32.tf32.f32 "
                "{%0,%1,%2,%3}, {%4,%5,%6,%7}, {%8,%9}, {%10,%11,%12,%13};\n"
                : "=f"(z0), "=f"(z1), "=f"(z2), "=f"(z3)
                : "r"(A0), "r"(A1), "r"(A2), "r"(A3),
                  "r"(wz0), "r"(wz1),
                  "f"(cb.x), "f"(cb.y), "f"(cb.x), "f"(cb.y));
            // lane's channels: n0 = 8j+2c (z0:eL, z2:eH), n1 = n0+1 (z1:eL, z3:eH)
            float h0 = fmaxf(z0, 0.f), h1 = fmaxf(z1, 0.f);
            float h2 = fmaxf(z2, 0.f), h3 = fmaxf(z3, 0.f);
            int n0 = 8 * j + 2 * c;
            ulonglong2 m0a = mps[n0 * 2],     m0b = mps[n0 * 2 + 1];
            ulonglong2 m1a = mps[n0 * 2 + 2], m1b = mps[n0 * 2 + 3];
            u64 hh0 = pk(h0, h0), hh1 = pk(h1, h1);
            u64 hh2 = pk(h2, h2), hh3 = pk(h3, h3);
            aL0 = f2fma(hh0, m0a.x, aL0); aL1 = f2fma(hh0, m0a.y, aL1);
            aL2 = f2fma(hh0, m0b.x, aL2); aL3 = f2fma(hh0, m0b.y, aL3);
            aL0 = f2fma(hh1, m1a.x, aL0); aL1 = f2fma(hh1, m1a.y, aL1);
            aL2 = f2fma(hh1, m1b.x, aL2); aL3 = f2fma(hh1, m1b.y, aL3);
            aH0 = f2fma(hh2, m0a.x, aH0); aH1 = f2fma(hh2, m0a.y, aH1);
            aH2 = f2fma(hh2, m0b.x, aH2); aH3 = f2fma(hh2, m0b.y, aH3);
            aH0 = f2fma(hh3, m1a.x, aH0); aH1 = f2fma(hh3, m1a.y, aH1);
            aH2 = f2fma(hh3, m1b.x, aH2); aH3 = f2fma(hh3, m1b.y, aH3);
        }

        // butterfly over the 4 c-lanes sharing edge rows g / g+8
#pragma unroll
        for (int off = 1; off <= 2; off <<= 1) {
            aL0 = f2add(aL0, __shfl_xor_sync(0xffffffffu, aL0, off));
            aL1 = f2add(aL1, __shfl_xor_sync(0xffffffffu, aL1, off));
            aL2 = f2add(aL2, __shfl_xor_sync(0xffffffffu, aL2, off));
            aL3 = f2add(aL3, __shfl_xor_sync(0xffffffffu, aL3, off));
            aH0 = f2add(aH0, __shfl_xor_sync(0xffffffffu, aH0, off));
            aH1 = f2add(aH1, __shfl_xor_sync(0xffffffffu, aH1, off));
            aH2 = f2add(aH2, __shfl_xor_sync(0xffffffffu, aH2, off));
            aH3 = f2add(aH3, __shfl_xor_sync(0xffffffffu, aH3, off));
        }
        u64 accL = (c == 0) ? aL0 : (c == 1) ? aL1 : (c == 2) ? aL2 : aL3;
        u64 accH = (c == 0) ? aH0 : (c == 1) ? aH1 : (c == 2) ? aH2 : aH3;

        int eL = base + g, eH = base + g + 8;
        if (eL < E) {
            float2 ea = *(const float2*)(edge_attr + eL * 8 + 2 * c);
            float lo, hi; upk(accL, lo, hi);
            *(float2*)(out + eL * 8 + 2 * c) = make_float2(ea.x + lo + czl,
                                                           ea.y + hi + czh);
        }
        if (eH < E) {
            float2 ea = *(const float2*)(edge_attr + eH * 8 + 2 * c);
            float lo, hi; upk(accH, lo, hi);
            *(float2*)(out + eH * 8 + 2 * c) = make_float2(ea.x + lo + czl,
                                                           ea.y + hi + czh);
        }
    }
}

// ------------------------- launch ------------------------------------------
extern "C" void kernel_launch(void* const* d_in, const int* in_sizes, int n_in,
                              void* d_out, int out_size) {
    const float* edge_attr = (const float*)d_in[0];
    const float* nf        = (const float*)d_in[1];
    const int*   ei        = (const int*)  d_in[2];
    // d_in[3..8] = edge encoder params: dead code in the reference, unused.
    const float* nW1   = (const float*)d_in[9];
    const float* nb1   = (const float*)d_in[10];
    const float* ngam  = (const float*)d_in[11];
    const float* nbet  = (const float*)d_in[12];
    const float* nW2   = (const float*)d_in[13];
    const float* nb2   = (const float*)d_in[14];
    const float* Wv    = (const float*)d_in[15];
    const float* bv    = (const float*)d_in[16];
    const float* Wo    = (const float*)d_in[17];
    const float* bo    = (const float*)d_in[18];
    const float* Wp    = (const float*)d_in[19];
    const float* bp    = (const float*)d_in[20];
    (void)n_in; (void)out_size;

    int E = in_sizes[0] / DDIM;
    const int* ei0 = ei;
    const int* ei1 = ei + E;
    float* out = (float*)d_out;
    int fullE = (E / 16) * 16;

    // BN statistics via tensor cores (longest chain starts immediately)
    stats_kernel<<<SGRID, 256>>>(nf, ei0, ei1, nW1, nb1, fullE);

    // weight folding (grid-parallel, R8 proven)
    fold_kernel<<<32, 256>>>(Wo, Wp, 0);    // R1 = Wo @ Wp
    fold_kernel<<<32, 256>>>(Wv, Wp, 1);    // R2 = Wv @ R1
    fold_kernel<<<32, 256>>>(nW2, Wp, 2);   // M  = nW2 @ R2

    // BN finalize + fragment packing
    reduce_kernel<<<HDIM, 256>>>(ngam, nbet, nf, ei0, ei1, nW1, nb1, fullE, E);
    final_kernel<<<1, 256>>>(nb2, bv, bo, bp, Wp, nW1);

    // MMA-z main pass: 16-edge tiles, TPW per warp, 8 warps/block
    int ntiles = (E + 15) / 16;
    int blocks = (ntiles + 8 * TPW - 1) / (8 * TPW);
    main_kernel<<<blocks, 256>>>(edge_attr, nf, ei0, ei1, nb1, out, E, ntiles);
}